// round 6
// baseline (speedup 1.0000x reference)
#include <cuda_runtime.h>
#include <climits>

#define Bn 64
#define Hn 512
#define Wn 512
#define HWn (Hn * Wn)
#define HW4 (HWn / 4)
#define ROWS_PER_BLOCK 16
#define BLOCKS_PER_BATCH (Hn / ROWS_PER_BLOCK)   // 32
#define GRID (Bn * BLOCKS_PER_BATCH)             // 2048
#define ITERS 4                                  // 4 rows per iteration

// Per-block partials — fully overwritten every launch before being read.
// Counter self-resets (elected warp zeroes it): deterministic across replays.
__device__ float    g_ps1[GRID];
__device__ float    g_ps2[GRID];
__device__ unsigned g_pflags[GRID];   // 32 bits: row r (0..15) -> bits 2r (cup), 2r+1 (disc)
__device__ unsigned g_count[Bn];

// Process 8 pixels (two 4-px rows) given 6 float4s; accumulate sums + row mask.
__device__ __forceinline__ void process_pair(
    const float4& v0a, const float4& v1a, const float4& v2a,
    const float4& v0b, const float4& v1b, const float4& v2b,
    int bitbase, float& s1, float& s2, unsigned& mask)
{
    const float* f0 = (const float*)&v0a;
    const float* f1 = (const float*)&v1a;
    const float* f2 = (const float*)&v2a;
    const float* h0 = (const float*)&v0b;
    const float* h1 = (const float*)&v1b;
    const float* h2 = (const float*)&v2b;
#pragma unroll
    for (int k = 0; k < 4; k++) {
        float a0 = f0[k], a1 = f1[k], a2 = f2[k];
        float m01 = fmaxf(a0, a1);
        bool  l2  = a2 > m01;
        bool  l1  = (a1 > a0) && !l2;
        if (l1) mask |= 1u << bitbase;
        if (l2) mask |= 1u << (bitbase + 1);
        float e0  = __expf(a0 - a1);
        float e2  = __expf(a2 - a1);
        float inv = __fdividef(1.0f, e0 + 1.0f + e2);
        s1 += inv;
        s2 += e2 * inv;
    }
#pragma unroll
    for (int k = 0; k < 4; k++) {
        float a0 = h0[k], a1 = h1[k], a2 = h2[k];
        float m01 = fmaxf(a0, a1);
        bool  l2  = a2 > m01;
        bool  l1  = (a1 > a0) && !l2;
        if (l1) mask |= 1u << (bitbase + 2);
        if (l2) mask |= 1u << (bitbase + 3);
        float e0  = __expf(a0 - a1);
        float e2  = __expf(a2 - a1);
        float inv = __fdividef(1.0f, e0 + 1.0f + e2);
        s1 += inv;
        s2 += e2 * inv;
    }
}

__global__ void __launch_bounds__(256) cdr_fused_kernel(const float* __restrict__ x,
                                                        float* __restrict__ out) {
    const int b    = blockIdx.x >> 5;     // batch
    const int g16  = blockIdx.x & 31;     // 16-row group
    const int tid  = threadIdx.x;
    const int rsel = tid >> 7;            // warp group 0: rows {0,1}+4it; 1: rows {2,3}+4it
    const int c4   = tid & 127;

    const float4* p = (const float4*)x;
    const int row0 = g16 * ROWS_PER_BLOCK + rsel * 2;
    const size_t base0 = (((size_t)b * 3 * HWn + (size_t)row0 * Wn) >> 2) + (size_t)c4;
    // iteration stride: 4 rows = 512 float4s

    float s1 = 0.f, s2 = 0.f;
    unsigned mask = 0;

    // ---- software-pipelined 4 iterations, register double buffer ----
    float4 A0 = p[base0];
    float4 A1 = p[base0 + HW4];
    float4 A2 = p[base0 + 2 * HW4];
    float4 A3 = p[base0 + 128];
    float4 A4 = p[base0 + HW4 + 128];
    float4 A5 = p[base0 + 2 * HW4 + 128];

#pragma unroll
    for (int it = 0; it < ITERS; it++) {
        float4 B0, B1, B2, B3, B4, B5;
        if (it < ITERS - 1) {
            const size_t nb = base0 + (size_t)(it + 1) * 512;
            B0 = p[nb];
            B1 = p[nb + HW4];
            B2 = p[nb + 2 * HW4];
            B3 = p[nb + 128];
            B4 = p[nb + HW4 + 128];
            B5 = p[nb + 2 * HW4 + 128];
        }
        const int bitbase = (it * 4 + rsel * 2) * 2;
        process_pair(A0, A1, A2, A3, A4, A5, bitbase, s1, s2, mask);
        if (it < ITERS - 1) {
            A0 = B0; A1 = B1; A2 = B2; A3 = B3; A4 = B4; A5 = B5;
        }
    }

    // ---- deterministic in-warp reduction (sums + mask OR in one tree) ----
#pragma unroll
    for (int o = 16; o > 0; o >>= 1) {
        s1   += __shfl_xor_sync(0xFFFFFFFFu, s1, o);
        s2   += __shfl_xor_sync(0xFFFFFFFFu, s2, o);
        mask |= __shfl_xor_sync(0xFFFFFFFFu, mask, o);
    }

    __shared__ float    sw1[8], sw2[8];
    __shared__ unsigned swf[8];
    const int wid = tid >> 5, lid = tid & 31;
    if (lid == 0) { sw1[wid] = s1; sw2[wid] = s2; swf[wid] = mask; }
    __syncthreads();

    // 7 of 8 warps retire immediately.
    if (wid != 0) return;

    // ---- warp 0: merge 8 warp partials warp-synchronously ----
    float    pv1 = (lid < 8) ? sw1[lid] : 0.f;
    float    pv2 = (lid < 8) ? sw2[lid] : 0.f;
    unsigned pf  = (lid < 8) ? swf[lid] : 0u;
#pragma unroll
    for (int o = 4; o > 0; o >>= 1) {
        pv1 += __shfl_xor_sync(0xFFFFFFFFu, pv1, o);
        pv2 += __shfl_xor_sync(0xFFFFFFFFu, pv2, o);
        pf  |= __shfl_xor_sync(0xFFFFFFFFu, pf, o);
    }

    int lastFlag = 0;
    if (lid == 0) {
        g_ps1[blockIdx.x]    = pv1;
        g_ps2[blockIdx.x]    = pv2;
        g_pflags[blockIdx.x] = pf;       // bit positions are absolute rows in block: plain OR valid
        __threadfence();
        lastFlag = (atomicAdd(&g_count[b], 1u) == BLOCKS_PER_BATCH - 1);
    }
    lastFlag = __shfl_sync(0xFFFFFFFFu, lastFlag, 0);
    if (!lastFlag) return;

    // ---- elected warp finalizes batch b: 32 partials, one per lane ----
    const int idx = b * BLOCKS_PER_BATCH + lid;
    float t1 = g_ps1[idx];
    float t2 = g_ps2[idx];
    unsigned fl = g_pflags[idx];

    int mn1 = INT_MAX, mx1 = -1, mn2 = INT_MAX, mx2 = -1;
    unsigned cupb  = fl & 0x55555555u;
    unsigned discb = fl & 0xAAAAAAAAu;
    if (cupb) {
        mn1 = lid * ROWS_PER_BLOCK + ((__ffs(cupb) - 1) >> 1);
        mx1 = lid * ROWS_PER_BLOCK + ((31 - __clz(cupb)) >> 1);
    }
    if (discb) {
        mn2 = lid * ROWS_PER_BLOCK + ((__ffs(discb) - 1) >> 1);
        mx2 = lid * ROWS_PER_BLOCK + ((31 - __clz(discb)) >> 1);
    }

#pragma unroll
    for (int o = 16; o > 0; o >>= 1) {
        t1  += __shfl_xor_sync(0xFFFFFFFFu, t1, o);
        t2  += __shfl_xor_sync(0xFFFFFFFFu, t2, o);
        mn1  = min(mn1, __shfl_xor_sync(0xFFFFFFFFu, mn1, o));
        mx1  = max(mx1, __shfl_xor_sync(0xFFFFFFFFu, mx1, o));
        mn2  = min(mn2, __shfl_xor_sync(0xFFFFFFFFu, mn2, o));
        mx2  = max(mx2, __shfl_xor_sync(0xFFFFFFFFu, mx2, o));
    }

    if (lid == 0) {
        const float inv_hw = 1.0f / (float)HWn;
        float cup_mean  = t1 * inv_hw;
        float disc_mean = t2 * inv_hw;
        float hcup  = (mx1 >= 0) ? (float)(mx1 - mn1) : 0.0f;
        float hdisc = (mx2 >= 0) ? (float)(mx2 - mn2) : 0.0f;
        float cdr = hcup / (hdisc + 1e-6f);
        out[b * 5 + 0] = cdr;
        out[b * 5 + 1] = disc_mean;
        out[b * 5 + 2] = cup_mean;
        out[b * 5 + 3] = disc_mean;
        out[b * 5 + 4] = cup_mean;
        g_count[b] = 0;   // self-reset: deterministic across graph replays
    }
}

extern "C" void kernel_launch(void* const* d_in, const int* in_sizes, int n_in,
                              void* d_out, int out_size) {
    const float* x = (const float*)d_in[0];
    float* out = (float*)d_out;
    (void)in_sizes; (void)n_in; (void)out_size;

    cdr_fused_kernel<<<GRID, 256>>>(x, out);
}

// round 7
// speedup vs baseline: 1.1232x; 1.1232x over previous
#include <cuda_runtime.h>
#include <climits>

#define Bn 64
#define Hn 512
#define Wn 512
#define HWn (Hn * Wn)
#define HW4 (HWn / 4)
#define ROWS_PER_BLOCK 8
#define BLOCKS_PER_BATCH (Hn / ROWS_PER_BLOCK)   // 64
#define GRID (Bn * BLOCKS_PER_BATCH)             // 4096

// Per-block partials — fully overwritten every launch before being read.
// Counter self-resets (elected warp zeroes it): deterministic across replays.
__device__ float    g_ps1[GRID];
__device__ float    g_ps2[GRID];
__device__ unsigned g_pflags[GRID];   // 16 bits: row r (0..7) -> bits 2r (cup), 2r+1 (disc)
__device__ unsigned g_count[Bn];

__global__ void __launch_bounds__(256, 3) cdr_fused_kernel(const float* __restrict__ x,
                                                           float* __restrict__ out) {
    const int b    = blockIdx.x >> 6;     // batch
    const int g8   = blockIdx.x & 63;     // 8-row group
    const int tid  = threadIdx.x;
    const int rsel = tid >> 7;            // which row within each 2-row tile

    // ---- Phase 1: 12 front-batched coalesced LDG.128 ----
    // Tile j (j=0..3) covers rows {2j, 2j+1} of this block's 8-row group.
    // Thread t handles float4 index t within the 2-row span (256 float4s).
    const float4* p = (const float4*)x;
    const size_t base = (((size_t)b * 3 * HWn + (size_t)g8 * ROWS_PER_BLOCK * Wn) >> 2)
                      + (size_t)tid;

    float4 L[4][3];
#pragma unroll
    for (int j = 0; j < 4; j++)
#pragma unroll
        for (int c = 0; c < 3; c++)
            L[j][c] = p[base + (size_t)j * 256 + (size_t)c * HW4];

    float s1 = 0.f, s2 = 0.f;
    unsigned mask = 0;   // absolute row bits within block

#pragma unroll
    for (int j = 0; j < 4; j++) {
        const float* a0p = (const float*)&L[j][0];
        const float* a1p = (const float*)&L[j][1];
        const float* a2p = (const float*)&L[j][2];
        const int bitbase = 2 * (2 * j + rsel);
        bool any1 = false, any2 = false;
#pragma unroll
        for (int k = 0; k < 4; k++) {
            float a0 = a0p[k], a1 = a1p[k], a2 = a2p[k];
            float m01 = fmaxf(a0, a1);
            bool  l2  = a2 > m01;
            bool  l1  = (a1 > a0) && !l2;
            any1 |= l1;
            any2 |= l2;
            float e0  = __expf(a0 - a1);
            float e2  = __expf(a2 - a1);
            float inv = __fdividef(1.0f, e0 + 1.0f + e2);
            s1 += inv;        // p(cup)
            s2 += e2 * inv;   // p(disc)
        }
        if (any1) mask |= 1u << bitbase;
        if (any2) mask |= 1u << (bitbase + 1);
    }

    // ---- Phase 2: deterministic in-warp reduction (sums + mask in one tree) ----
#pragma unroll
    for (int o = 16; o > 0; o >>= 1) {
        s1   += __shfl_xor_sync(0xFFFFFFFFu, s1, o);
        s2   += __shfl_xor_sync(0xFFFFFFFFu, s2, o);
        mask |= __shfl_xor_sync(0xFFFFFFFFu, mask, o);
    }

    __shared__ float    sw1[8], sw2[8];
    __shared__ unsigned swf[8];
    const int wid = tid >> 5, lid = tid & 31;
    if (lid == 0) { sw1[wid] = s1; sw2[wid] = s2; swf[wid] = mask; }
    __syncthreads();

    // 7 of 8 warps retire immediately — slots host the next block's loads.
    if (wid != 0) return;

    // ---- Phase 3: warp 0 merges 8 warp partials warp-synchronously ----
    float    pv1 = (lid < 8) ? sw1[lid] : 0.f;
    float    pv2 = (lid < 8) ? sw2[lid] : 0.f;
    unsigned pf  = (lid < 8) ? swf[lid] : 0u;
#pragma unroll
    for (int o = 4; o > 0; o >>= 1) {
        pv1 += __shfl_xor_sync(0xFFFFFFFFu, pv1, o);
        pv2 += __shfl_xor_sync(0xFFFFFFFFu, pv2, o);
        pf  |= __shfl_xor_sync(0xFFFFFFFFu, pf, o);
    }

    int lastFlag = 0;
    if (lid == 0) {
        g_ps1[blockIdx.x]    = pv1;
        g_ps2[blockIdx.x]    = pv2;
        g_pflags[blockIdx.x] = pf;   // absolute row bits: plain OR across warps is valid
        __threadfence();
        lastFlag = (atomicAdd(&g_count[b], 1u) == BLOCKS_PER_BATCH - 1);
    }
    lastFlag = __shfl_sync(0xFFFFFFFFu, lastFlag, 0);
    if (!lastFlag) return;

    // ---- Phase 4: elected warp finalizes batch b (64 partials, 2 per lane) ----
    float t1 = 0.f, t2 = 0.f;
    int mn1 = INT_MAX, mx1 = -1, mn2 = INT_MAX, mx2 = -1;
#pragma unroll
    for (int h = 0; h < 2; h++) {
        const int e   = lid + 32 * h;                // block index within batch
        const int idx = b * BLOCKS_PER_BATCH + e;
        t1 += g_ps1[idx];
        t2 += g_ps2[idx];
        unsigned fl = g_pflags[idx];
        unsigned cupb  = fl & 0x5555u;
        unsigned discb = fl & 0xAAAAu;
        if (cupb) {
            mn1 = min(mn1, e * ROWS_PER_BLOCK + ((__ffs(cupb) - 1) >> 1));
            mx1 = max(mx1, e * ROWS_PER_BLOCK + ((31 - __clz(cupb)) >> 1));
        }
        if (discb) {
            mn2 = min(mn2, e * ROWS_PER_BLOCK + ((__ffs(discb) - 1) >> 1));
            mx2 = max(mx2, e * ROWS_PER_BLOCK + ((31 - __clz(discb)) >> 1));
        }
    }
#pragma unroll
    for (int o = 16; o > 0; o >>= 1) {
        t1  += __shfl_xor_sync(0xFFFFFFFFu, t1, o);
        t2  += __shfl_xor_sync(0xFFFFFFFFu, t2, o);
        mn1  = min(mn1, __shfl_xor_sync(0xFFFFFFFFu, mn1, o));
        mx1  = max(mx1, __shfl_xor_sync(0xFFFFFFFFu, mx1, o));
        mn2  = min(mn2, __shfl_xor_sync(0xFFFFFFFFu, mn2, o));
        mx2  = max(mx2, __shfl_xor_sync(0xFFFFFFFFu, mx2, o));
    }

    if (lid == 0) {
        const float inv_hw = 1.0f / (float)HWn;
        float cup_mean  = t1 * inv_hw;
        float disc_mean = t2 * inv_hw;
        float hcup  = (mx1 >= 0) ? (float)(mx1 - mn1) : 0.0f;
        float hdisc = (mx2 >= 0) ? (float)(mx2 - mn2) : 0.0f;
        float cdr = hcup / (hdisc + 1e-6f);
        out[b * 5 + 0] = cdr;
        out[b * 5 + 1] = disc_mean;
        out[b * 5 + 2] = cup_mean;
        out[b * 5 + 3] = disc_mean;
        out[b * 5 + 4] = cup_mean;
        g_count[b] = 0;   // self-reset: deterministic across graph replays
    }
}

extern "C" void kernel_launch(void* const* d_in, const int* in_sizes, int n_in,
                              void* d_out, int out_size) {
    const float* x = (const float*)d_in[0];
    float* out = (float*)d_out;
    (void)in_sizes; (void)n_in; (void)out_size;

    cdr_fused_kernel<<<GRID, 256>>>(x, out);
}